// round 17
// baseline (speedup 1.0000x reference)
#include <cuda_runtime.h>
#include <cuda_fp16.h>
#include <cstdint>
#include <cstring>

// NT-Xent contrastive loss, sm_103 baseline ISA. fp16 HMMA (f16 acc).
// SINGLE persistent kernel (148 CTAs = 1 wave):
//   - 128 CTAs prep one 32-pair chunk each (zn = normalize(z)*sqrt(2*log2e),
//     pos, diag, g_S zeros) and publish per-band arrival counters (4/band).
//   - GEMM (round-16 structure: 32 indep HMMA chains of depth 4, symmetric
//     tiles, pair-major flattened schedule) starts immediately; consumers
//     spin on a band's counter only before first touching that band.
//   - device-wide barrier -> distributed finish, ticket CTA writes out and
//     resets counters (graph-replay safe). u64 fixed-point = deterministic.

#define N2    8192
#define DD    128
#define NHALF 4096
#define RSTRIDE 272
#define TILE_SM (128 * RSTRIDE)          // 34816
#define SM_COLRED (4 * TILE_SM)          // A + 3 B stages before colred
#define SMEM_TOTAL (4 * TILE_SM + 2048)
#define FXS  68719476736.0f              // 2^36
#define FXL  1099511627776.0f            // 2^40
#define NCTA 148

__device__ __align__(16) __half g_zn[(size_t)N2 * DD];   // normalize(z)*sqrt(2*log2e)
__device__ unsigned long long g_S[N2];
__device__ unsigned long long g_acc;
__device__ unsigned int g_bandcnt[64];   // arrivals per band (full at 4)
__device__ unsigned int g_allcnt;        // prep chunks done (full at 128)
__device__ unsigned int g_bar, g_tick;
__device__ float g_pos[N2];
__device__ float g_diag[N2];

// ---------------- PTX helpers ----------------
__device__ __forceinline__ uint32_t smem_u32(const void* p) {
    uint32_t a;
    asm("{ .reg .u64 t; cvta.to.shared.u64 t, %1; cvt.u32.u64 %0, t; }" : "=r"(a) : "l"(p));
    return a;
}
__device__ __forceinline__ void cp16(uint32_t dst, const void* src) {
    asm volatile("cp.async.cg.shared.global [%0], [%1], 16;" :: "r"(dst), "l"(src));
}
#define CP_COMMIT() asm volatile("cp.async.commit_group;" ::: "memory")
#define CP_WAIT2()  asm volatile("cp.async.wait_group 2;" ::: "memory")
#define CP_WAIT1()  asm volatile("cp.async.wait_group 1;" ::: "memory")
#define CP_WAIT0()  asm volatile("cp.async.wait_group 0;" ::: "memory")

#define LDSM4(r0, r1, r2, r3, addr)                                              \
    asm volatile("ldmatrix.sync.aligned.m8n8.x4.shared.b16 {%0,%1,%2,%3}, [%4];" \
                 : "=r"(r0), "=r"(r1), "=r"(r2), "=r"(r3) : "r"(addr))

#define MMA16816H(c, a, b0, b1)                                                \
    asm volatile("mma.sync.aligned.m16n8k16.row.col.f16.f16.f16.f16 "          \
                 "{%0,%1}, {%2,%3,%4,%5}, {%6,%7}, {%0,%1};"                   \
                 : "+r"((c)[0]), "+r"((c)[1])                                  \
                 : "r"((a)[0]), "r"((a)[1]), "r"((a)[2]), "r"((a)[3]),         \
                   "r"(b0), "r"(b1))

__device__ __forceinline__ float fast_lg2(float x) {
    float y; asm("lg2.approx.f32 %0, %1;" : "=f"(y) : "f"(x)); return y;
}
__device__ __forceinline__ __half2 u2h2(uint32_t u) {
    __half2 h; memcpy(&h, &u, 4); return h;
}

// prep one pair (one warp): zn rows w, w+NHALF; pos; diag; zero g_S rows.
__device__ __forceinline__ void prep_pair(const float* __restrict__ zi,
                                          const float* __restrict__ zj,
                                          int w, int lane) {
    float4 a = reinterpret_cast<const float4*>(zi + (size_t)w * DD)[lane];
    float4 b = reinterpret_cast<const float4*>(zj + (size_t)w * DD)[lane];
    float sa = a.x * a.x + a.y * a.y + a.z * a.z + a.w * a.w;
    float sb = b.x * b.x + b.y * b.y + b.z * b.z + b.w * b.w;
    float dp = a.x * b.x + a.y * b.y + a.z * b.z + a.w * b.w;
#pragma unroll
    for (int o = 16; o > 0; o >>= 1) {
        sa += __shfl_xor_sync(0xffffffffu, sa, o);
        sb += __shfl_xor_sync(0xffffffffu, sb, o);
        dp += __shfl_xor_sync(0xffffffffu, dp, o);
    }
    float ia = rsqrtf(sa), ib = rsqrtf(sb);
    const float SQ = 1.69864361f;           // sqrt(2*log2(e))
    float iaS = ia * SQ, ibS = ib * SQ;

    __half qa[4], qb[4];
    qa[0]=__float2half_rn(a.x*iaS); qa[1]=__float2half_rn(a.y*iaS);
    qa[2]=__float2half_rn(a.z*iaS); qa[3]=__float2half_rn(a.w*iaS);
    qb[0]=__float2half_rn(b.x*ibS); qb[1]=__float2half_rn(b.y*ibS);
    qb[2]=__float2half_rn(b.z*ibS); qb[3]=__float2half_rn(b.w*ibS);

    float da = 0.f, db = 0.f;
#pragma unroll
    for (int k = 0; k < 4; ++k) {
        float fa = __half2float(qa[k]), fb = __half2float(qb[k]);
        da += fa * fa; db += fb * fb;
    }
#pragma unroll
    for (int o = 16; o > 0; o >>= 1) {
        da += __shfl_xor_sync(0xffffffffu, da, o);
        db += __shfl_xor_sync(0xffffffffu, db, o);
    }
    if (lane == 0) {
        float p = 2.0f * dp * ia * ib;
        g_pos[w] = p; g_pos[w + NHALF] = p;
        g_diag[w]         = exp2f(da);
        g_diag[w + NHALF] = exp2f(db);
        g_S[w] = 0ull; g_S[w + NHALF] = 0ull;
    }
    uint2 u;
    memcpy(&u, qa, 8); reinterpret_cast<uint2*>(g_zn + (size_t)w * DD)[lane] = u;
    memcpy(&u, qb, 8); reinterpret_cast<uint2*>(g_zn + (size_t)(w + NHALF) * DD)[lane] = u;
}

__device__ __forceinline__ void load_tile(uint32_t dstBase, const __half* src, int tid) {
#pragma unroll
    for (int p = 0; p < 8; ++p) {
        int id = p * 256 + tid;
        int row = id >> 4, ch = id & 15;
        cp16(dstBase + row * RSTRIDE + ch * 16,
             reinterpret_cast<const char*>(src) + row * 256 + ch * 16);
    }
}

__device__ __forceinline__ void wait_band(int k, int& allr) {
    if (allr) return;
    if (atomicAdd(&g_allcnt, 0u) >= 128u) { allr = 1; return; }
    while (atomicAdd(&g_bandcnt[k], 0u) < 4u) __nanosleep(32);
}

// ---------------- fused persistent kernel ----------------
__global__ __launch_bounds__(256, 1) void fused_kernel(
    const float* __restrict__ zi, const float* __restrict__ zj,
    float* __restrict__ out) {
    extern __shared__ unsigned char smem[];
    const uint32_t sb   = smem_u32(smem);
    const uint32_t smA  = sb;
    const uint32_t smB0 = sb + TILE_SM;                          // 3 stages
    float* colred = reinterpret_cast<float*>(smem + SM_COLRED);  // [4 wm][128]

    const int tid = threadIdx.x, wid = tid >> 5, lane = tid & 31;
    const int wm = wid & 3;           // 4 row groups (32 rows)
    const int wn = wid >> 2;          // 2 col groups (64 cols)
    const int bx = blockIdx.x;
    int allr = 0;

    // ======== phase 0: prep chunk (CTAs 0..127; 32 pairs each) ========
    if (bx < 128) {
        int base = bx * 32;
#pragma unroll 1
        for (int j = 0; j < 4; ++j)
            prep_pair(zi, zj, base + wid * 4 + j, lane);
        __threadfence();
        __syncthreads();
        if (tid == 0) {
            atomicAdd(&g_bandcnt[bx >> 2], 1u);
            atomicAdd(&g_bandcnt[32 + (bx >> 2)], 1u);
            atomicAdd(&g_allcnt, 1u);
        }
    }

    // ======== phase 1: symmetric-tile GEMM (flag-gated band access) ========
    int t    = bx * 14 + (bx < 8 ? bx : 8);
    int tEnd = t + 14 + (bx < 8 ? 1 : 0);

    const uint32_t aOff = (uint32_t)(lane & 15) * RSTRIDE + (uint32_t)((lane >> 4) << 4);
    const uint32_t bOff = (uint32_t)((lane & 7) + ((lane & 16) ? 8 : 0)) * RSTRIDE +
                          (uint32_t)((lane & 8) ? 16 : 0);
    const __half2 zero2 = __float2half2_rn(0.f);

#pragma unroll 1
    while (t < tEnd) {
        int q = t / 65, r = t - q * 65;
        int len1 = 64 - q;
        int I, J0, navail;
        if (r < len1) { I = q;      J0 = q + r;  navail = len1 - r; }
        else          { int r2 = r - len1;
                        I = 63 - q; J0 = I + r2; navail = (q + 1) - r2; }
        const int n = (tEnd - t < navail) ? (tEnd - t) : navail;
        t += n;

        if (tid == 0) {
            wait_band(I, allr);
            wait_band(J0, allr);
            if (n > 1) wait_band(J0 + 1, allr);
        }
        __syncthreads();   // bands ready + previous-run reads complete
        load_tile(smA, g_zn + (size_t)I * 128 * DD, tid);
        CP_COMMIT();
        load_tile(smB0, g_zn + (size_t)J0 * 128 * DD, tid);
        CP_COMMIT();
        if (n > 1)
            load_tile(smB0 + TILE_SM, g_zn + (size_t)(J0 + 1) * 128 * DD, tid);
        CP_COMMIT();
        CP_WAIT2();
        __syncthreads();

        uint32_t afr[2][8][4];
        {
            const uint32_t aBase = smA + (uint32_t)(wm * 32) * RSTRIDE + aOff;
#pragma unroll
            for (int mb = 0; mb < 2; ++mb)
#pragma unroll
                for (int ks = 0; ks < 8; ++ks)
                    LDSM4(afr[mb][ks][0], afr[mb][ks][1], afr[mb][ks][2], afr[mb][ks][3],
                          aBase + (uint32_t)(mb * 16) * RSTRIDE + (uint32_t)(ks * 32));
        }

        float frow[2][2] = {{0.f,0.f},{0.f,0.f}};

#pragma unroll 1
        for (int tt = 0; tt < n; ++tt) {
            const int J = J0 + tt;
            const int s = tt % 3;
            CP_WAIT1();
            if (tid == 0 && tt + 2 < n) wait_band(J + 2, allr);
            __syncthreads();
            if (tt + 2 < n)
                load_tile(smB0 + (uint32_t)((tt + 2) % 3) * TILE_SM,
                          g_zn + (size_t)(J + 2) * 128 * DD, tid);
            CP_COMMIT();

            const uint32_t bBase = smB0 + (uint32_t)s * TILE_SM +
                                   (uint32_t)(wn * 64) * RSTRIDE + bOff;

            // 32 independent chains of depth 4
            uint32_t accv[2][2][4][2][2];
#pragma unroll
            for (int h = 0; h < 2; ++h)
#pragma unroll
                for (int mb = 0; mb < 2; ++mb)
#pragma unroll
                    for (int nq = 0; nq < 4; ++nq)
#pragma unroll
                        for (int nb = 0; nb < 2; ++nb)
                            { accv[h][mb][nq][nb][0] = 0u; accv[h][mb][nq][nb][1] = 0u; }

            uint32_t bfr[2][4][4];
#pragma unroll
            for (int nq = 0; nq < 4; ++nq)
                LDSM4(bfr[0][nq][0], bfr[0][nq][1], bfr[0][nq][2], bfr[0][nq][3],
                      bBase + (uint32_t)(nq * 16) * RSTRIDE);
#pragma unroll
            for (int ks = 0; ks < 8; ++ks) {
                const int cur = ks & 1, nxt = cur ^ 1;
                if (ks + 1 < 8) {
#pragma unroll
                    for (int nq = 0; nq < 4; ++nq)
                        LDSM4(bfr[nxt][nq][0], bfr[nxt][nq][1], bfr[nxt][nq][2], bfr[nxt][nq][3],
                              bBase + (uint32_t)(nq * 16) * RSTRIDE + (uint32_t)((ks + 1) * 32));
                }
                const int h = ks & 1;
#pragma unroll
                for (int mb = 0; mb < 2; ++mb)
#pragma unroll
                    for (int nq = 0; nq < 4; ++nq) {
                        MMA16816H(accv[h][mb][nq][0], afr[mb][ks], bfr[cur][nq][0], bfr[cur][nq][1]);
                        MMA16816H(accv[h][mb][nq][1], afr[mb][ks], bfr[cur][nq][2], bfr[cur][nq][3]);
                    }
            }

            // epilogue: merge K-halves, exp2, row + col sums
            __half2 sumr0[2] = {zero2, zero2};
            __half2 sumr8[2] = {zero2, zero2};
#pragma unroll
            for (int nq = 0; nq < 4; ++nq)
#pragma unroll
                for (int nb = 0; nb < 2; ++nb) {
                    __half2 colv = zero2;
#pragma unroll
                    for (int mb = 0; mb < 2; ++mb) {
                        __half2 s0 = __hadd2(u2h2(accv[0][mb][nq][nb][0]),
                                             u2h2(accv[1][mb][nq][nb][0]));
                        __half2 s1 = __hadd2(u2h2(accv[0][mb][nq][nb][1]),
                                             u2h2(accv[1][mb][nq][nb][1]));
                        __half2 e0 = h2exp2(s0);
                        __half2 e1 = h2exp2(s1);
                        sumr0[mb] = __hadd2(sumr0[mb], e0);
                        sumr8[mb] = __hadd2(sumr8[mb], e1);
                        colv = __hadd2(colv, __hadd2(e0, e1));
                    }
                    colv = __hadd2(colv, __shfl_xor_sync(0xffffffffu, colv, 4));
                    colv = __hadd2(colv, __shfl_xor_sync(0xffffffffu, colv, 8));
                    colv = __hadd2(colv, __shfl_xor_sync(0xffffffffu, colv, 16));
                    if (lane < 4) {
                        float2 c = __half22float2(colv);
                        int col = wn * 64 + nq * 16 + nb * 8 + lane * 2;
                        colred[wm * 128 + col + 0] = c.x;
                        colred[wm * 128 + col + 1] = c.y;
                    }
                }
#pragma unroll
            for (int mb = 0; mb < 2; ++mb) {
                float2 f0 = __half22float2(sumr0[mb]);
                float2 f1 = __half22float2(sumr8[mb]);
                frow[mb][0] += f0.x + f0.y;
                frow[mb][1] += f1.x + f1.y;
            }

            __syncthreads();   // colred ready; stage-s reads complete
            if (J != I && tid < 128) {
                float v = colred[tid] + colred[128 + tid] +
                          colred[256 + tid] + colred[384 + tid];
                atomicAdd(&g_S[J * 128 + tid], __float2ull_rn(v * FXS));
            }
        }

        // row flush for band I (per run)
#pragma unroll
        for (int mb = 0; mb < 2; ++mb)
#pragma unroll
            for (int h = 0; h < 2; ++h) {
                frow[mb][h] += __shfl_xor_sync(0xffffffffu, frow[mb][h], 1);
                frow[mb][h] += __shfl_xor_sync(0xffffffffu, frow[mb][h], 2);
            }
        if ((lane & 3) == 0) {
            int qd = lane >> 2;
            int rbase = I * 128 + wm * 32 + qd;
#pragma unroll
            for (int mb = 0; mb < 2; ++mb) {
                atomicAdd(&g_S[rbase + mb * 16 + 0], __float2ull_rn(frow[mb][0] * FXS));
                atomicAdd(&g_S[rbase + mb * 16 + 8], __float2ull_rn(frow[mb][1] * FXS));
            }
        }
    }
    CP_WAIT0();

    // ======== device-wide barrier (148 CTAs = 1 wave) ========
    __threadfence();
    __syncthreads();
    if (tid == 0) {
        atomicAdd(&g_bar, 1u);
        while (atomicAdd(&g_bar, 0u) < NCTA) __nanosleep(64);
    }
    __syncthreads();

    // ======== phase 2: distributed finish ========
    {
        const float LN2 = 0.6931471805599453f;
        if (bx < 32) {
            int i = bx * 256 + tid;
            float S = __ull2float_rn(__ldcg(&g_S[i])) * (1.0f / FXS);
            float term = fast_lg2(S - __ldcg(&g_diag[i])) * LN2 - __ldcg(&g_pos[i]);
            unsigned long long fx = __float2ull_rn(term * FXL);
#pragma unroll
            for (int o = 16; o > 0; o >>= 1)
                fx += __shfl_xor_sync(0xffffffffu, fx, o);
            if (lane == 0) atomicAdd(&g_acc, fx);
        }
        __threadfence();
        __syncthreads();
        if (tid == 0) {
            unsigned int tk = atomicAdd(&g_tick, 1u);
            if (tk == NCTA - 1) {
                __threadfence();
                unsigned long long total = atomicAdd(&g_acc, 0ull);
                out[0] = (float)((double)total * (1.0 / 1099511627776.0) / (double)N2);
                // reset for next graph replay
                g_bar = 0u; g_tick = 0u; g_allcnt = 0u; g_acc = 0ull;
#pragma unroll
                for (int k = 0; k < 64; ++k) g_bandcnt[k] = 0u;
            }
        }
    }
}

// ---------------- launch ----------------
extern "C" void kernel_launch(void* const* d_in, const int* in_sizes, int n_in,
                              void* d_out, int out_size) {
    const float* zi = (const float*)d_in[0];
    const float* zj = (const float*)d_in[1];
    cudaFuncSetAttribute(fused_kernel, cudaFuncAttributeMaxDynamicSharedMemorySize,
                         SMEM_TOTAL);
    fused_kernel<<<NCTA, 256, SMEM_TOTAL>>>(zi, zj, (float*)d_out);
}